// round 1
// baseline (speedup 1.0000x reference)
#include <cuda_runtime.h>
#include <math.h>
#include <math_constants.h>

#define BATCH 64
#define DIM   768
#define HW    3136          // 56*56
#define FREQ  256
#define NE    16
#define TOPK  4

// scratch (device globals: no allocation allowed in kernel_launch)
__device__ float g_pooled[BATCH * DIM];
__device__ float g_logits[BATCH * NE];

// ---------------------------------------------------------------------------
// Kernel A: pooled = x.mean(axis=(2,3)).  One warp per (b,dim) row.
// Row = 3136 contiguous fp32 = 784 float4. HBM-bound: 616.6 MB read.
// ---------------------------------------------------------------------------
__global__ void pool_kernel(const float* __restrict__ x) {
    const int warp_id = (blockIdx.x * blockDim.x + threadIdx.x) >> 5;
    const int lane = threadIdx.x & 31;
    if (warp_id >= BATCH * DIM) return;

    const float4* row = reinterpret_cast<const float4*>(x + (size_t)warp_id * HW);
    float s = 0.0f;
    // 784 float4 per row = 24 full strides of 32 + 16 tail
#pragma unroll
    for (int j = 0; j < 24; ++j) {
        float4 v = row[lane + 32 * j];
        s += (v.x + v.y) + (v.z + v.w);
    }
    if (lane < 16) {
        float4 v = row[768 + lane];
        s += (v.x + v.y) + (v.z + v.w);
    }
#pragma unroll
    for (int m = 16; m; m >>= 1) s += __shfl_xor_sync(0xffffffffu, s, m);
    if (lane == 0) g_pooled[warp_id] = s * (1.0f / (float)HW);
}

// ---------------------------------------------------------------------------
// Kernel B: logits[b,e] = pooled[b]·gate_w[e] + freq_emb[b]·freq_gate_w[e]
// 64 blocks (one per batch row) x 512 threads (warp = expert).
// Weights (48KB + 16KB) are L2-resident and reused by all 64 blocks.
// ---------------------------------------------------------------------------
__global__ void logits_kernel(const float* __restrict__ freq_emb,
                              const float* __restrict__ gate_w,
                              const float* __restrict__ fgate_w) {
    const int b    = blockIdx.x;
    const int e    = threadIdx.x >> 5;   // 0..15
    const int lane = threadIdx.x & 31;

    const float4* pr  = reinterpret_cast<const float4*>(g_pooled + b * DIM);
    const float4* gr  = reinterpret_cast<const float4*>(gate_w  + e * DIM);
    float s = 0.0f;
#pragma unroll
    for (int j = 0; j < 6; ++j) {            // 192 float4 / 32 lanes
        float4 a = pr[lane + 32 * j];
        float4 w = gr[lane + 32 * j];
        s += a.x * w.x + a.y * w.y + a.z * w.z + a.w * w.w;
    }
    const float4* fr  = reinterpret_cast<const float4*>(freq_emb + b * FREQ);
    const float4* fgr = reinterpret_cast<const float4*>(fgate_w  + e * FREQ);
#pragma unroll
    for (int j = 0; j < 2; ++j) {            // 64 float4 / 32 lanes
        float4 a = fr[lane + 32 * j];
        float4 w = fgr[lane + 32 * j];
        s += a.x * w.x + a.y * w.y + a.z * w.z + a.w * w.w;
    }
#pragma unroll
    for (int m = 16; m; m >>= 1) s += __shfl_xor_sync(0xffffffffu, s, m);
    if (lane == 0) g_logits[b * NE + e] = s;
}

// ---------------------------------------------------------------------------
// Kernel C: softmax / top-k / gates / aux loss. Single block, 1024 threads.
// Thread = (b,e); each 16-lane group = one batch row (xor masks 1,2,4,8 stay
// inside the group). Deterministic smem reductions for the losses.
// Output layout (float32): gates[64*16] | top_k_indices[64*4] | top_k_values[64*4] | aux_loss
// ---------------------------------------------------------------------------
__global__ void finish_kernel(const float* __restrict__ noise,
                              const float* __restrict__ complexity,
                              float* __restrict__ out) {
    __shared__ float s_clean[BATCH * NE];
    __shared__ float s_p[BATCH * NE];

    const int tid  = threadIdx.x;          // 0..1023
    const int b    = tid >> 4;
    const int e    = tid & 15;
    const int lane = tid & 31;
    const int half = lane & 16;            // base lane of my 16-lane group

    const float noise_std = 1.0f / (float)NE;
    const float logit = g_logits[tid];
    const float noisy = logit + noise[tid] * noise_std;

    // clean softmax over the 16-lane row group
    float cm = logit;
#pragma unroll
    for (int m = 8; m; m >>= 1) cm = fmaxf(cm, __shfl_xor_sync(0xffffffffu, cm, m));
    float ce = expf(logit - cm);
    float cs = ce;
#pragma unroll
    for (int m = 8; m; m >>= 1) cs += __shfl_xor_sync(0xffffffffu, cs, m);
    const float clean = ce / cs;

    // noisy softmax
    float nm = noisy;
#pragma unroll
    for (int m = 8; m; m >>= 1) nm = fmaxf(nm, __shfl_xor_sync(0xffffffffu, nm, m));
    float ne_ = expf(noisy - nm);
    float ns = ne_;
#pragma unroll
    for (int m = 8; m; m >>= 1) ns += __shfl_xor_sync(0xffffffffu, ns, m);
    const float score = ne_ / ns;

    // rank of my noisy logit within the row (ties: lower index wins, jax top_k)
    int rank = 0;
#pragma unroll
    for (int j = 0; j < 16; ++j) {
        float vj = __shfl_sync(0xffffffffu, noisy, half + j);
        rank += (vj > noisy) || (vj == noisy && j < e);
    }

    // threshold = k-th largest noisy logit (rank == TOPK-1)
    float thr = (rank == TOPK - 1) ? noisy : -CUDART_INF_F;
#pragma unroll
    for (int m = 8; m; m >>= 1) thr = fmaxf(thr, __shfl_xor_sync(0xffffffffu, thr, m));

    // outputs: gates / indices / values
    out[tid] = (rank < TOPK) ? score : 0.0f;
    if (rank < TOPK) {
        out[BATCH * NE + b * TOPK + rank]                 = (float)e;  // indices
        out[BATCH * NE + BATCH * TOPK + b * TOPK + rank]  = score;     // values
    }

    // p = 1 - norm_cdf((thr - logit)/noise_std) = 0.5*erfc(arg/sqrt(2))
    const float p = 0.5f * erfcf((thr - logit) * (float)NE * 0.70710678118654752f);

    s_clean[tid] = clean;
    s_p[tid]     = p;
    __syncthreads();

    if (tid < 32) {
        float imp = 0.0f, pm = 0.0f;
        if (tid < 16) {
            for (int bb = 0; bb < BATCH; ++bb) {
                imp += s_clean[bb * NE + tid];
                pm  += s_p[bb * NE + tid];
            }
            imp *= complexity[tid];
            pm  *= (1.0f / (float)BATCH);
        }
        // mean over the 16 expert lanes (lanes 16..31 hold zeros, reduced separately)
        float im = imp, pmn = pm;
#pragma unroll
        for (int m = 8; m; m >>= 1) {
            im  += __shfl_xor_sync(0xffffffffu, im,  m);
            pmn += __shfl_xor_sync(0xffffffffu, pmn, m);
        }
        im  *= (1.0f / (float)NE);
        pmn *= (1.0f / (float)NE);
        float dv = (tid < 16) ? (imp - im)  * (imp - im)  : 0.0f;
        float dp = (tid < 16) ? (pm  - pmn) * (pm  - pmn) : 0.0f;
#pragma unroll
        for (int m = 8; m; m >>= 1) {
            dv += __shfl_xor_sync(0xffffffffu, dv, m);
            dp += __shfl_xor_sync(0xffffffffu, dp, m);
        }
        if (tid == 0) {
            // var_unbiased = dv/(n-1); loss = var / (mean+1e-8)^2
            float imp_loss  = (dv / (float)(NE - 1)) / ((im  + 1e-8f) * (im  + 1e-8f));
            float load_loss = (dp / (float)(NE - 1)) / ((pmn + 1e-8f) * (pmn + 1e-8f));
            out[BATCH * NE + 2 * BATCH * TOPK] = 0.5f * imp_loss + 0.5f * load_loss;
        }
    }
}

// ---------------------------------------------------------------------------
extern "C" void kernel_launch(void* const* d_in, const int* in_sizes, int n_in,
                              void* d_out, int out_size) {
    const float* x         = (const float*)d_in[0];
    const float* freq_emb  = (const float*)d_in[1];
    const float* gate_w    = (const float*)d_in[2];
    const float* fgate_w   = (const float*)d_in[3];
    const float* complexity= (const float*)d_in[4];
    const float* noise     = (const float*)d_in[5];
    float* out = (float*)d_out;

    // A: pooling — 49152 warps, 8 warps/block
    const int total_warps = BATCH * DIM;
    pool_kernel<<<total_warps / 8, 256>>>(x);

    // B: logits — one block per batch row, warp per expert
    logits_kernel<<<BATCH, 512>>>(freq_emb, gate_w, fgate_w);

    // C: epilogue — single block
    finish_kernel<<<1, BATCH * NE>>>(noise, complexity, out);
}

// round 2
// speedup vs baseline: 1.0110x; 1.0110x over previous
#include <cuda_runtime.h>
#include <math.h>
#include <math_constants.h>

#define BATCH 64
#define DIM   768
#define HW    3136          // 56*56
#define FREQ  256
#define NE    16
#define TOPK  4

// scratch (device globals: no allocation allowed in kernel_launch)
__device__ float g_logits_main[BATCH * NE];   // atomic-accumulated pooled @ gate_w.T
__device__ float g_logits_freq[BATCH * NE];   // freq_emb @ freq_gate_w.T (plain writes)

// ---------------------------------------------------------------------------
// Kernel A (fused): pooled mean over HW + gating GEMM via per-warp atomics.
// One warp per (b,d) row of x. After xor-reduce, every lane holds the full
// row sum; lanes 0..15 atomically add pooled*gate_w[e,d] into g_logits_main.
// Warps with d < NE additionally compute the freq-emb dot for (b, e=d).
// HBM-bound: 616.6 MB streaming read of x.
// ---------------------------------------------------------------------------
__global__ void __launch_bounds__(256) pool_gate_kernel(
    const float* __restrict__ x,
    const float* __restrict__ gate_w,
    const float* __restrict__ freq_emb,
    const float* __restrict__ fgate_w) {

    const int warp_id = (blockIdx.x * blockDim.x + threadIdx.x) >> 5;
    const int lane = threadIdx.x & 31;
    const int b = warp_id / DIM;
    const int d = warp_id - b * DIM;

    const float4* row = reinterpret_cast<const float4*>(x + (size_t)warp_id * HW);

    // 784 float4 per row: 3 batches of (8 x 32-lane strides) + 16 tail
    float s = 0.0f;
#pragma unroll
    for (int t = 0; t < 3; ++t) {
        float4 v[8];
#pragma unroll
        for (int k = 0; k < 8; ++k)
            v[k] = __ldcs(&row[lane + 32 * (t * 8 + k)]);
#pragma unroll
        for (int k = 0; k < 8; ++k)
            s += (v[k].x + v[k].y) + (v[k].z + v[k].w);
    }
    if (lane < 16) {
        float4 v = __ldcs(&row[768 + lane]);
        s += (v.x + v.y) + (v.z + v.w);
    }
#pragma unroll
    for (int m = 16; m; m >>= 1) s += __shfl_xor_sync(0xffffffffu, s, m);

    // gating contribution: every lane has the full sum now
    const float pooled = s * (1.0f / (float)HW);
    if (lane < NE) {
        atomicAdd(&g_logits_main[b * NE + lane], pooled * gate_w[lane * DIM + d]);
    }

    // freq-emb logits ride along on the 1024 warps with d < NE
    if (d < NE) {
        const int e = d;
        const float4* fr  = reinterpret_cast<const float4*>(freq_emb + b * FREQ);
        const float4* fgr = reinterpret_cast<const float4*>(fgate_w  + e * FREQ);
        float f = 0.0f;
#pragma unroll
        for (int j = 0; j < 2; ++j) {   // 64 float4 / 32 lanes
            float4 a = fr[lane + 32 * j];
            float4 w = fgr[lane + 32 * j];
            f += a.x * w.x + a.y * w.y + a.z * w.z + a.w * w.w;
        }
#pragma unroll
        for (int m = 16; m; m >>= 1) f += __shfl_xor_sync(0xffffffffu, f, m);
        if (lane == 0) g_logits_freq[b * NE + e] = f;
    }
}

// ---------------------------------------------------------------------------
// Kernel B: softmax / top-k / gates / aux loss. Single block, 1024 threads.
// Thread = (b,e); each 16-lane group = one batch row.
// Output (float32): gates[64*16] | top_k_indices[64*4] | top_k_values[64*4] | aux_loss
// ---------------------------------------------------------------------------
__global__ void finish_kernel(const float* __restrict__ noise,
                              const float* __restrict__ complexity,
                              float* __restrict__ out) {
    __shared__ float s_clean[BATCH * NE];
    __shared__ float s_p[BATCH * NE];

    const int tid  = threadIdx.x;          // 0..1023
    const int b    = tid >> 4;
    const int e    = tid & 15;
    const int lane = tid & 31;
    const int half = lane & 16;            // base lane of my 16-lane group

    const float noise_std = 1.0f / (float)NE;
    const float logit = g_logits_main[tid] + g_logits_freq[tid];
    const float noisy = logit + noise[tid] * noise_std;

    // clean softmax over the 16-lane row group
    float cm = logit;
#pragma unroll
    for (int m = 8; m; m >>= 1) cm = fmaxf(cm, __shfl_xor_sync(0xffffffffu, cm, m));
    float ce = expf(logit - cm);
    float cs = ce;
#pragma unroll
    for (int m = 8; m; m >>= 1) cs += __shfl_xor_sync(0xffffffffu, cs, m);
    const float clean = ce / cs;

    // noisy softmax
    float nm = noisy;
#pragma unroll
    for (int m = 8; m; m >>= 1) nm = fmaxf(nm, __shfl_xor_sync(0xffffffffu, nm, m));
    float ne_ = expf(noisy - nm);
    float ns = ne_;
#pragma unroll
    for (int m = 8; m; m >>= 1) ns += __shfl_xor_sync(0xffffffffu, ns, m);
    const float score = ne_ / ns;

    // rank of my noisy logit within the row (ties: lower index wins, jax top_k)
    int rank = 0;
#pragma unroll
    for (int j = 0; j < 16; ++j) {
        float vj = __shfl_sync(0xffffffffu, noisy, half + j);
        rank += (vj > noisy) || (vj == noisy && j < e);
    }

    // threshold = k-th largest noisy logit (rank == TOPK-1)
    float thr = (rank == TOPK - 1) ? noisy : -CUDART_INF_F;
#pragma unroll
    for (int m = 8; m; m >>= 1) thr = fmaxf(thr, __shfl_xor_sync(0xffffffffu, thr, m));

    // outputs: gates / indices / values
    out[tid] = (rank < TOPK) ? score : 0.0f;
    if (rank < TOPK) {
        out[BATCH * NE + b * TOPK + rank]                 = (float)e;  // indices
        out[BATCH * NE + BATCH * TOPK + b * TOPK + rank]  = score;     // values
    }

    // p = 1 - norm_cdf((thr - logit)/noise_std) = 0.5*erfc(arg/sqrt(2))
    const float p = 0.5f * erfcf((thr - logit) * (float)NE * 0.70710678118654752f);

    s_clean[tid] = clean;
    s_p[tid]     = p;
    __syncthreads();

    if (tid < 32) {
        float imp = 0.0f, pm = 0.0f;
        if (tid < 16) {
            for (int bb = 0; bb < BATCH; ++bb) {
                imp += s_clean[bb * NE + tid];
                pm  += s_p[bb * NE + tid];
            }
            imp *= complexity[tid];
            pm  *= (1.0f / (float)BATCH);
        }
        float im = imp, pmn = pm;
#pragma unroll
        for (int m = 8; m; m >>= 1) {
            im  += __shfl_xor_sync(0xffffffffu, im,  m);
            pmn += __shfl_xor_sync(0xffffffffu, pmn, m);
        }
        im  *= (1.0f / (float)NE);
        pmn *= (1.0f / (float)NE);
        float dv = (tid < 16) ? (imp - im)  * (imp - im)  : 0.0f;
        float dp = (tid < 16) ? (pm  - pmn) * (pm  - pmn) : 0.0f;
#pragma unroll
        for (int m = 8; m; m >>= 1) {
            dv += __shfl_xor_sync(0xffffffffu, dv, m);
            dp += __shfl_xor_sync(0xffffffffu, dp, m);
        }
        if (tid == 0) {
            float imp_loss  = (dv / (float)(NE - 1)) / ((im  + 1e-8f) * (im  + 1e-8f));
            float load_loss = (dp / (float)(NE - 1)) / ((pmn + 1e-8f) * (pmn + 1e-8f));
            out[BATCH * NE + 2 * BATCH * TOPK] = 0.5f * imp_loss + 0.5f * load_loss;
        }
    }
}

// ---------------------------------------------------------------------------
extern "C" void kernel_launch(void* const* d_in, const int* in_sizes, int n_in,
                              void* d_out, int out_size) {
    const float* x          = (const float*)d_in[0];
    const float* freq_emb   = (const float*)d_in[1];
    const float* gate_w     = (const float*)d_in[2];
    const float* fgate_w    = (const float*)d_in[3];
    const float* complexity = (const float*)d_in[4];
    const float* noise      = (const float*)d_in[5];
    float* out = (float*)d_out;

    // zero the atomic accumulator (graph-capturable memset node)
    void* logits_ptr = nullptr;
    cudaGetSymbolAddress(&logits_ptr, g_logits_main);
    cudaMemsetAsync(logits_ptr, 0, BATCH * NE * sizeof(float));

    // A: fused pooling + gating GEMM — 49152 warps, 8 warps/block
    pool_gate_kernel<<<(BATCH * DIM) / 8, 256>>>(x, gate_w, freq_emb, fgate_w);

    // B: epilogue — single block
    finish_kernel<<<1, BATCH * NE>>>(noise, complexity, out);
}